// round 12
// baseline (speedup 1.0000x reference)
#include <cuda_runtime.h>
#include <cstdint>

// ---------------------------------------------------------------------------
// TripletFeatures: M=41, p=20.  Index set: |m*n|<=20, n>=m, |m|+|n|<=20, K=173.
// out[b,c,k] = Re( S_mn * E[p+n,c] ) + (m!=n) * Re( S_nm * E[p+m,c] )
//   with S_xy = sum_c E[p+x,c]*conj(E[p+x+y,c])
// Output contract (verified): float32 (B, 2, K), REAL PART ONLY.
//
// Champion structure (1 warp/batch, constexpr u|v table, direct coalesced
// stores, warp-sync only) with COMPONENT-PLANE smem layout: Esh[c][pos]
// (float2 at byte 8*pos -> bank class pos mod 16). Consecutive-n windows
// become conflict-free for V and W loads (vs guaranteed 2-way conflicts in
// the interleaved layout where class = pos mod 8).
// ---------------------------------------------------------------------------

constexpr int K    = 173;
constexpr int WPB  = 8;     // warps (batches) per block
constexpr int ME   = 82;    // floats per batch per input array (41 pos * 2 c)
constexpr int PLN  = 48;    // padded plane stride (float2 units)

struct Tab { unsigned short e[K]; };   // u | v<<8  (w = u+v-20 derived)

__host__ __device__ constexpr Tab make_tab() {
    Tab t{}; int cnt = 0;
    for (int m = -20; m <= 20; ++m) {
        for (int n = -20; n <= 20; ++n) {
            int am = m < 0 ? -m : m;
            int an = n < 0 ? -n : n;
            if (am * an <= 20 && n >= m && am + an <= 20) {
                t.e[cnt] = (unsigned short)((m + 20) | ((n + 20) << 8));
                ++cnt;
            }
        }
    }
    return t;
}

__global__ void __launch_bounds__(WPB * 32, 8)
triplet_kernel(const float* __restrict__ er,
               const float* __restrict__ ei,
               float* __restrict__ out,
               int B)
{
    static constexpr Tab TAB = make_tab();

    // Two component planes per warp: plane c holds (re, im) of E[pos, c].
    __shared__ float2 Esh[WPB][2 * PLN];

    const int w    = threadIdx.x >> 5;
    const int lane = threadIdx.x & 31;
    const long long b = (long long)blockIdx.x * WPB + w;
    if (b >= B) return;

    // Stage this warp's batch. Input float index j = 2*pos + c.
    const float* rbase = er + b * ME;
    const float* ibase = ei + b * ME;
    #pragma unroll
    for (int j = lane; j < ME; j += 32) {
        const int pos = j >> 1;
        const int c   = j & 1;
        Esh[w][c * PLN + pos] = make_float2(rbase[j], ibase[j]);
    }
    __syncwarp();

    const float2* E0 = Esh[w];         // component 0 plane
    const float2* E1 = Esh[w] + PLN;   // component 1 plane
    float* ob  = out + b * (2 * K);
    float* obK = ob + K;

    #pragma unroll
    for (int i = 0; i < 6; ++i) {
        const int k = lane + 32 * i;
        if (i < 5 || k < K) {              // iterations 0..4 unguarded
            const unsigned e = TAB.e[k];
            const int u  = e & 0xff;       // p + m
            const int v  = e >> 8;         // p + n
            const int ww = u + v - 20;     // p + m + n

            const float2 U0 = E0[u];
            const float2 U1 = E1[u];
            const float2 V0 = E0[v];
            const float2 V1 = E1[v];
            const float2 W0 = E0[ww];
            const float2 W1 = E1[ww];

            const float Sr = U0.x * W0.x + U0.y * W0.y + U1.x * W1.x + U1.y * W1.y;
            const float Si = U0.y * W0.x - U0.x * W0.y + U1.y * W1.x - U1.x * W1.y;

            float o0 = Sr * V0.x - Si * V0.y;
            float o1 = Sr * V1.x - Si * V1.y;

            if (u != v) {
                const float Tr = V0.x * W0.x + V0.y * W0.y + V1.x * W1.x + V1.y * W1.y;
                const float Ti = V0.y * W0.x - V0.x * W0.y + V1.y * W1.x - V1.x * W1.y;
                o0 += Tr * U0.x - Ti * U0.y;
                o1 += Tr * U1.x - Ti * U1.y;
            }

            ob[k]  = o0;    // out[b, 0, k]
            obK[k] = o1;    // out[b, 1, k]
        }
    }
}

extern "C" void kernel_launch(void* const* d_in, const int* in_sizes, int n_in,
                              void* d_out, int out_size)
{
    const float* er = (const float*)d_in[0];   // E_real (B, 41, 2) float32
    const float* ei = (const float*)d_in[1];   // E_imag (B, 41, 2) float32
    float* out = (float*)d_out;                // float32 (B, 2, K) real parts

    const int B = in_sizes[0] / ME;
    const int grid = (B + WPB - 1) / WPB;

    triplet_kernel<<<grid, WPB * 32>>>(er, ei, out, B);
}